// round 6
// baseline (speedup 1.0000x reference)
#include <cuda_runtime.h>
#include <mma.h>
#include <math.h>
#include <cstdint>
#include <stdint.h>

using namespace nvcuda;

#define Bn 2
#define Sn 2048
#define Dn 768
#define Hn 12
#define DHn 64
#define Fn 3072
#define Ln 2
#define BSn (Bn*Sn)
#define BHn (Bn*Hn)
#define NKT 16               // Sn / 128 key tiles

// ---------------- scratch ----------------
__device__ float g_h  [BSn*Dn];
__device__ float g_qh [BSn*Dn];
__device__ float g_kh [BSn*Dn];
__device__ float g_vh [BSn*Dn];
__device__ float g_o  [BSn*Dn];
__device__ float g_t  [BSn*Dn];
__device__ float g_ff [BSn*Fn];
__device__ float g_rmax[BHn*Sn];
__device__ float g_rinv[BHn*Sn];

// ---------------- cp.async helpers ----------------
__device__ __forceinline__ void cp_async16(uint32_t saddr, const void* gaddr) {
    asm volatile("cp.async.cg.shared.global [%0], [%1], 16;\n" :: "r"(saddr), "l"(gaddr));
}
#define CP_COMMIT() asm volatile("cp.async.commit_group;\n" ::)
#define CP_WAIT1()  asm volatile("cp.async.wait_group 1;\n" ::)
#define CP_WAIT0()  asm volatile("cp.async.wait_group 0;\n" ::)

// ---------------- embedding + sinusoidal PE ----------------
__global__ void embed_kernel(const int* __restrict__ x, const float* __restrict__ emb,
                             float* __restrict__ h)
{
    int row = blockIdx.x;
    int s   = row % Sn;
    long tok = x[row];
    const float* er = emb + tok * (long)Dn;
    float* hr = h + (long)row * Dn;
    const float c = -logf(10000.0f) / (float)Dn;
    for (int j = threadIdx.x; j < Dn; j += blockDim.x) {
        float div = expf((float)(j & ~1) * c);
        float ang = (float)s * div;
        float pe = (j & 1) ? cosf(ang) : sinf(ang);
        hr[j] = er[j] + pe;
    }
}

// ================= fused attention =================
// Per CTA: 128 q-rows of one (b,h). 8 warps in 4x2.
// S-MMA: BMxBN = 128x128, K=64.  O-MMA: 128x64, K=128.
#define LDQ 68
#define LDS 132
#define SMEM_STATS ((128*LDQ*2 + 128*LDS)*4)            // 137216
#define SMEM_AV    ((128*LDQ*3 + 128*LDS + 256)*4)      // 173056

__global__ __launch_bounds__(256, 1)
void attn_stats_kernel(const float* __restrict__ qh, const float* __restrict__ kh,
                       float* __restrict__ rmax, float* __restrict__ rinv)
{
    extern __shared__ float sm[];
    float* Qs = sm;                    // [128][LDQ]
    float* Ks = Qs + 128*LDQ;          // [128][LDQ]
    float* Ss = Ks + 128*LDQ;          // [128][LDS]

    const int z  = blockIdx.y;
    const int qb = blockIdx.x * 128;
    const int tid  = threadIdx.x;
    const int warp = tid >> 5;
    const int wm = (warp & 3) * 32;
    const int wn = (warp >> 2) * 64;

    const float* Qg = qh + ((long)z * Sn + qb) * DHn;
    const float* Kg = kh + (long)z * Sn * DHn;
    const uint32_t sQ = (uint32_t)__cvta_generic_to_shared(Qs);
    const uint32_t sK = (uint32_t)__cvta_generic_to_shared(Ks);

    // load Q tile once
    for (int e = tid; e < 128*16; e += 256) {
        int r = e >> 4, c4 = (e & 15) * 4;
        cp_async16(sQ + (r*LDQ + c4)*4, Qg + r*DHn + c4);
    }
    CP_COMMIT();

    const int row = tid >> 1, hf = tid & 1;
    float m = -1e30f, ssum = 0.f;

    for (int kt = 0; kt < NKT; kt++) {
        __syncthreads();
        for (int e = tid; e < 128*16; e += 256) {
            int r = e >> 4, c4 = (e & 15) * 4;
            cp_async16(sK + (r*LDQ + c4)*4, Kg + (long)(kt*128 + r)*DHn + c4);
        }
        CP_COMMIT(); CP_WAIT0();
        __syncthreads();

        wmma::fragment<wmma::accumulator,16,16,8,float> accS[2][4];
#pragma unroll
        for (int i = 0; i < 2; i++)
#pragma unroll
            for (int j = 0; j < 4; j++) wmma::fill_fragment(accS[i][j], 0.f);
#pragma unroll
        for (int kf = 0; kf < 8; kf++) {
            wmma::fragment<wmma::matrix_a,16,16,8,wmma::precision::tf32,wmma::row_major> af[2];
#pragma unroll
            for (int i = 0; i < 2; i++) {
                wmma::load_matrix_sync(af[i], Qs + (wm + i*16)*LDQ + kf*8, LDQ);
#pragma unroll
                for (int e = 0; e < af[i].num_elements; e++)
                    af[i].x[e] = wmma::__float_to_tf32(af[i].x[e]);
            }
            wmma::fragment<wmma::matrix_b,16,16,8,wmma::precision::tf32,wmma::col_major> bf[4];
#pragma unroll
            for (int j = 0; j < 4; j++) {
                wmma::load_matrix_sync(bf[j], Ks + (wn + j*16)*LDQ + kf*8, LDQ);
#pragma unroll
                for (int e = 0; e < bf[j].num_elements; e++)
                    bf[j].x[e] = wmma::__float_to_tf32(bf[j].x[e]);
            }
#pragma unroll
            for (int i = 0; i < 2; i++)
#pragma unroll
                for (int j = 0; j < 4; j++)
                    wmma::mma_sync(accS[i][j], af[i], bf[j], accS[i][j]);
        }
#pragma unroll
        for (int i = 0; i < 2; i++)
#pragma unroll
            for (int j = 0; j < 4; j++)
                wmma::store_matrix_sync(Ss + (wm + i*16)*LDS + wn + j*16,
                                        accS[i][j], LDS, wmma::mem_row_major);
        __syncthreads();

        // per-row tile stats (2 threads per row)
        const float* rp = Ss + row*LDS + hf*64;
        float lm = -1e30f;
#pragma unroll
        for (int c = 0; c < 16; c++) {
            float4 v = *(const float4*)(rp + c*4);
            lm = fmaxf(lm, fmaxf(fmaxf(v.x, v.y), fmaxf(v.z, v.w)));
        }
        lm *= 0.125f;
        float pm = __shfl_xor_sync(0xffffffffu, lm, 1);
        float tm = fmaxf(lm, pm);
        float ls = 0.f;
#pragma unroll
        for (int c = 0; c < 16; c++) {
            float4 v = *(const float4*)(rp + c*4);
            ls += __expf(v.x*0.125f - tm) + __expf(v.y*0.125f - tm)
                + __expf(v.z*0.125f - tm) + __expf(v.w*0.125f - tm);
        }
        float ps = __shfl_xor_sync(0xffffffffu, ls, 1);
        float ts = ls + ps;
        float mn = fmaxf(m, tm);
        ssum = ssum * __expf(m - mn) + ts * __expf(tm - mn);
        m = mn;
    }

    if (hf == 0) {
        rmax[(long)z*Sn + qb + row] = m;
        rinv[(long)z*Sn + qb + row] = 1.f / ssum;
    }
}

__global__ __launch_bounds__(256, 1)
void attn_av_kernel(const float* __restrict__ qh, const float* __restrict__ kh,
                    const float* __restrict__ vh,
                    const float* __restrict__ rmax, const float* __restrict__ rinv,
                    float* __restrict__ maps, float* __restrict__ og)
{
    extern __shared__ float sm[];
    float* Qs = sm;                    // [128][LDQ]
    float* Ks = Qs + 128*LDQ;
    float* Vs = Ks + 128*LDQ;
    float* Ss = Vs + 128*LDQ;          // [128][LDS]
    float* rm = Ss + 128*LDS;          // [128]
    float* ri = rm + 128;              // [128]

    const int z  = blockIdx.y;
    const int qb = blockIdx.x * 128;
    const int tid  = threadIdx.x;
    const int warp = tid >> 5;
    const int wm   = (warp & 3) * 32;
    const int wn   = (warp >> 2) * 64;   // S columns
    const int wno  = (warp >> 2) * 32;   // O columns

    const float* Qg = qh + ((long)z * Sn + qb) * DHn;
    const float* Kg = kh + (long)z * Sn * DHn;
    const float* Vg = vh + (long)z * Sn * DHn;
    float* Mg = maps + (long)z * Sn * Sn;
    const uint32_t sQ = (uint32_t)__cvta_generic_to_shared(Qs);
    const uint32_t sK = (uint32_t)__cvta_generic_to_shared(Ks);
    const uint32_t sV = (uint32_t)__cvta_generic_to_shared(Vs);

    if (tid < 128) rm[tid] = rmax[(long)z*Sn + qb + tid];
    else           ri[tid-128] = rinv[(long)z*Sn + qb + tid - 128];

    for (int e = tid; e < 128*16; e += 256) {
        int r = e >> 4, c4 = (e & 15) * 4;
        cp_async16(sQ + (r*LDQ + c4)*4, Qg + r*DHn + c4);
    }
    CP_COMMIT();

    wmma::fragment<wmma::accumulator,16,16,8,float> accO[2][2];
#pragma unroll
    for (int i = 0; i < 2; i++)
#pragma unroll
        for (int j = 0; j < 2; j++) wmma::fill_fragment(accO[i][j], 0.f);

    for (int kt = 0; kt < NKT; kt++) {
        __syncthreads();
        for (int e = tid; e < 128*16; e += 256) {
            int r = e >> 4, c4 = (e & 15) * 4;
            cp_async16(sK + (r*LDQ + c4)*4, Kg + (long)(kt*128 + r)*DHn + c4);
            cp_async16(sV + (r*LDQ + c4)*4, Vg + (long)(kt*128 + r)*DHn + c4);
        }
        CP_COMMIT(); CP_WAIT0();
        __syncthreads();

        // S = Q @ K^T
        wmma::fragment<wmma::accumulator,16,16,8,float> accS[2][4];
#pragma unroll
        for (int i = 0; i < 2; i++)
#pragma unroll
            for (int j = 0; j < 4; j++) wmma::fill_fragment(accS[i][j], 0.f);
#pragma unroll
        for (int kf = 0; kf < 8; kf++) {
            wmma::fragment<wmma::matrix_a,16,16,8,wmma::precision::tf32,wmma::row_major> af[2];
#pragma unroll
            for (int i = 0; i < 2; i++) {
                wmma::load_matrix_sync(af[i], Qs + (wm + i*16)*LDQ + kf*8, LDQ);
#pragma unroll
                for (int e = 0; e < af[i].num_elements; e++)
                    af[i].x[e] = wmma::__float_to_tf32(af[i].x[e]);
            }
            wmma::fragment<wmma::matrix_b,16,16,8,wmma::precision::tf32,wmma::col_major> bf[4];
#pragma unroll
            for (int j = 0; j < 4; j++) {
                wmma::load_matrix_sync(bf[j], Ks + (wn + j*16)*LDQ + kf*8, LDQ);
#pragma unroll
                for (int e = 0; e < bf[j].num_elements; e++)
                    bf[j].x[e] = wmma::__float_to_tf32(bf[j].x[e]);
            }
#pragma unroll
            for (int i = 0; i < 2; i++)
#pragma unroll
                for (int j = 0; j < 4; j++)
                    wmma::mma_sync(accS[i][j], af[i], bf[j], accS[i][j]);
        }
#pragma unroll
        for (int i = 0; i < 2; i++)
#pragma unroll
            for (int j = 0; j < 4; j++)
                wmma::store_matrix_sync(Ss + (wm + i*16)*LDS + wn + j*16,
                                        accS[i][j], LDS, wmma::mem_row_major);
        __syncthreads();

        // normalize in smem + write probs tile to maps (coalesced)
#pragma unroll
        for (int p = 0; p < 16; p++) {
            int e = tid + p*256;
            int r = e >> 5, c4 = (e & 31) * 4;
            float4 v = *(const float4*)&Ss[r*LDS + c4];
            float M = rm[r], I = ri[r];
            v.x = __expf(v.x*0.125f - M) * I;
            v.y = __expf(v.y*0.125f - M) * I;
            v.z = __expf(v.z*0.125f - M) * I;
            v.w = __expf(v.w*0.125f - M) * I;
            *(float4*)&Ss[r*LDS + c4] = v;
            *(float4*)&Mg[(long)(qb + r)*Sn + kt*128 + c4] = v;
        }
        __syncthreads();

        // O += P @ V
#pragma unroll
        for (int kf = 0; kf < 16; kf++) {
            wmma::fragment<wmma::matrix_a,16,16,8,wmma::precision::tf32,wmma::row_major> af[2];
#pragma unroll
            for (int i = 0; i < 2; i++) {
                wmma::load_matrix_sync(af[i], Ss + (wm + i*16)*LDS + kf*8, LDS);
#pragma unroll
                for (int e = 0; e < af[i].num_elements; e++)
                    af[i].x[e] = wmma::__float_to_tf32(af[i].x[e]);
            }
            wmma::fragment<wmma::matrix_b,16,16,8,wmma::precision::tf32,wmma::row_major> bf[2];
#pragma unroll
            for (int j = 0; j < 2; j++) {
                wmma::load_matrix_sync(bf[j], Vs + (kf*8)*LDQ + wno + j*16, LDQ);
#pragma unroll
                for (int e = 0; e < bf[j].num_elements; e++)
                    bf[j].x[e] = wmma::__float_to_tf32(bf[j].x[e]);
            }
#pragma unroll
            for (int i = 0; i < 2; i++)
#pragma unroll
                for (int j = 0; j < 2; j++)
                    wmma::mma_sync(accO[i][j], af[i], bf[j], accO[i][j]);
        }
    }

    // write O to merged [b,s,D] layout (stage via Qs)
    __syncthreads();
#pragma unroll
    for (int i = 0; i < 2; i++)
#pragma unroll
        for (int j = 0; j < 2; j++)
            wmma::store_matrix_sync(Qs + (wm + i*16)*LDQ + wno + j*16,
                                    accO[i][j], LDQ, wmma::mem_row_major);
    __syncthreads();
    const int b = z / Hn, hh = z % Hn;
#pragma unroll
    for (int p = 0; p < 8; p++) {
        int e = tid + p*256;
        int r = e >> 4, c4 = (e & 15) * 4;
        float4 v = *(const float4*)&Qs[r*LDQ + c4];
        *(float4*)&og[(long)(b*Sn + qb + r)*Dn + hh*DHn + c4] = v;
    }
}

// ---------------- pipelined TF32 tensor-core GEMM (dense path) ----------------
// MODE: 0 plain, 1 heads (QKV -> [b,h,s,d]).  MULTI: z selects {B0,B1,B2}.
template<int BM, int BN, int MODE, bool MULTI>
__global__ __launch_bounds__(256, 2)
void gemm_tc(const float* __restrict__ A,
             const float* B0, const float* B1, const float* B2,
             const float* bias0, const float* bias1, const float* bias2,
             float* C0, float* C1, float* C2,
             int M, int N, int K, int lda, int ldb, int ldc, int relu)
{
    constexpr int BK = 32;
    constexpr int STAGES = 3;
    constexpr int LDA_S = BK + 4;
    constexpr int LDB_S = BN + 4;
    constexpr int LDC_S = BN + 4;
    constexpr int WARPS_M = 4, WARPS_N = 2;
    constexpr int WM = BM / WARPS_M;
    constexpr int WN = BN / WARPS_N;
    constexpr int FM = WM / 16;
    constexpr int FN = WN / 16;

    extern __shared__ char smem_raw[];
    float* As = (float*)smem_raw;
    float* Bs = As + STAGES * BM * LDA_S;
    float* Cs = (float*)smem_raw;

    const int z = blockIdx.z;
    const float* Bm; const float* bias; float* C;
    if (MULTI) {
        Bm   = (z == 0) ? B0 : ((z == 1) ? B1 : B2);
        bias = (z == 0) ? bias0 : ((z == 1) ? bias1 : bias2);
        C    = (z == 0) ? C0 : ((z == 1) ? C1 : C2);
    } else {
        Bm = B0; bias = bias0; C = C0;
    }

    const int bm = blockIdx.y * BM;
    const int bn = blockIdx.x * BN;
    const int tid = threadIdx.x;
    const int warp = tid >> 5;
    const int wm = (warp % WARPS_M) * WM;
    const int wn = (warp / WARPS_M) * WN;

    const uint32_t sAs = (uint32_t)__cvta_generic_to_shared(As);
    const uint32_t sBs = (uint32_t)__cvta_generic_to_shared(Bs);

    wmma::fragment<wmma::accumulator, 16, 16, 8, float> acc[FM][FN];
#pragma unroll
    for (int i = 0; i < FM; i++)
#pragma unroll
        for (int j = 0; j < FN; j++) wmma::fill_fragment(acc[i][j], 0.0f);

    const int kIters = K / BK;

    auto load_stage = [&](int st, int ki) {
        if (ki >= kIters) return;
        const int k0 = ki * BK;
        constexpr int NVA = BM * BK / 4;
#pragma unroll
        for (int e = tid; e < NVA; e += 256) {
            int m  = e / (BK / 4);
            int kv = (e % (BK / 4)) * 4;
            cp_async16(sAs + ((st * BM + m) * LDA_S + kv) * 4,
                       A + (long)(bm + m) * lda + k0 + kv);
        }
        constexpr int NVB = BK * BN / 4;
#pragma unroll
        for (int e = tid; e < NVB; e += 256) {
            int k  = e / (BN / 4);
            int nv = (e % (BN / 4)) * 4;
            cp_async16(sBs + ((st * BK + k) * LDB_S + nv) * 4,
                       Bm + (long)(k0 + k) * ldb + bn + nv);
        }
    };

    for (int s = 0; s < STAGES - 1; s++) { load_stage(s, s); CP_COMMIT(); }

    for (int ki = 0; ki < kIters; ki++) {
        CP_WAIT1();
        __syncthreads();
        load_stage((ki + STAGES - 1) % STAGES, ki + STAGES - 1);
        CP_COMMIT();

        const int st = ki % STAGES;
        const float* Ast = As + st * BM * LDA_S;
        const float* Bst = Bs + st * BK * LDB_S;
#pragma unroll
        for (int kf = 0; kf < BK / 8; kf++) {
            wmma::fragment<wmma::matrix_a, 16, 16, 8, wmma::precision::tf32, wmma::row_major> af[FM];
#pragma unroll
            for (int i = 0; i < FM; i++) {
                wmma::load_matrix_sync(af[i], Ast + (wm + i * 16) * LDA_S + kf * 8, LDA_S);
#pragma unroll
                for (int e = 0; e < af[i].num_elements; e++)
                    af[i].x[e] = wmma::__float_to_tf32(af[i].x[e]);
            }
            wmma::fragment<wmma::matrix_b, 16, 16, 8, wmma::precision::tf32, wmma::row_major> bf[FN];
#pragma unroll
            for (int j = 0; j < FN; j++) {
                wmma::load_matrix_sync(bf[j], Bst + (kf * 8) * LDB_S + wn + j * 16, LDB_S);
#pragma unroll
                for (int e = 0; e < bf[j].num_elements; e++)
                    bf[j].x[e] = wmma::__float_to_tf32(bf[j].x[e]);
            }
#pragma unroll
            for (int i = 0; i < FM; i++)
#pragma unroll
                for (int j = 0; j < FN; j++)
                    wmma::mma_sync(acc[i][j], af[i], bf[j], acc[i][j]);
        }
    }

    CP_WAIT0();
    __syncthreads();

#pragma unroll
    for (int i = 0; i < FM; i++)
#pragma unroll
        for (int j = 0; j < FN; j++)
            wmma::store_matrix_sync(Cs + (wm + i * 16) * LDC_S + wn + j * 16,
                                    acc[i][j], LDC_S, wmma::mem_row_major);
    __syncthreads();

    constexpr int NVC = BM * BN / 4;
#pragma unroll 4
    for (int e = tid; e < NVC; e += 256) {
        int m  = e / (BN / 4);
        int nv = (e % (BN / 4)) * 4;
        float4 v = *(const float4*)&Cs[m * LDC_S + nv];
        if (bias) {
            int c = bn + nv;
            v.x += bias[c]; v.y += bias[c + 1]; v.z += bias[c + 2]; v.w += bias[c + 3];
        }
        if (relu) {
            v.x = fmaxf(v.x, 0.f); v.y = fmaxf(v.y, 0.f);
            v.z = fmaxf(v.z, 0.f); v.w = fmaxf(v.w, 0.f);
        }
        if (MODE == 0) {
            *(float4*)&C[(long)(bm + m) * ldc + bn + nv] = v;
        } else {
            int r = bm + m, c = bn + nv;
            int b = r >> 11, s = r & (Sn - 1);
            int hh = c >> 6, d = c & 63;
            *(float4*)&C[((((long)b * Hn + hh) * Sn + s) << 6) + d] = v;
        }
    }
}

// ---------------- residual add + LayerNorm ----------------
__global__ void add_ln_kernel(const float* __restrict__ x, const float* __restrict__ d,
                              const float* __restrict__ g, const float* __restrict__ bb,
                              float* __restrict__ out)
{
    int row = blockIdx.x;
    int t = threadIdx.x;
    __shared__ float red[256];
    float v[3];
    float s = 0.f;
#pragma unroll
    for (int i = 0; i < 3; i++) {
        int c = t + i*256;
        v[i] = x[(long)row*Dn + c] + d[(long)row*Dn + c];
        s += v[i];
    }
    red[t] = s; __syncthreads();
    for (int o = 128; o > 0; o >>= 1) { if (t < o) red[t] += red[t+o]; __syncthreads(); }
    float mu = red[0] / (float)Dn;
    __syncthreads();
    float s2 = 0.f;
#pragma unroll
    for (int i = 0; i < 3; i++) { float dv = v[i] - mu; s2 += dv*dv; }
    red[t] = s2; __syncthreads();
    for (int o = 128; o > 0; o >>= 1) { if (t < o) red[t] += red[t+o]; __syncthreads(); }
    float inv = rsqrtf(red[0] / (float)Dn + 1e-5f);
    __syncthreads();
#pragma unroll
    for (int i = 0; i < 3; i++) {
        int c = t + i*256;
        out[(long)row*Dn + c] = (v[i] - mu) * inv * g[c] + bb[c];
    }
}

// ---------------- host side ----------------
#define SYM_PTR(sym) ([]{ void* p_; cudaGetSymbolAddress(&p_, sym); return (float*)p_; }())

#define SMEM_NN128 ((3*(128*36 + 32*132))*4)            // 105984

extern "C" void kernel_launch(void* const* d_in, const int* in_sizes, int n_in,
                              void* d_out, int out_size)
{
    const int*   x    = (const int*)  d_in[0];
    const float* emb  = (const float*)d_in[1];
    const float* Wq   = (const float*)d_in[2];
    const float* bq   = (const float*)d_in[3];
    const float* Wk   = (const float*)d_in[4];
    const float* bk   = (const float*)d_in[5];
    const float* Wv   = (const float*)d_in[6];
    const float* bv   = (const float*)d_in[7];
    const float* Wo   = (const float*)d_in[8];
    const float* bo   = (const float*)d_in[9];
    const float* ln1g = (const float*)d_in[10];
    const float* ln1b = (const float*)d_in[11];
    const float* ln2g = (const float*)d_in[12];
    const float* ln2b = (const float*)d_in[13];
    const float* W1   = (const float*)d_in[14];
    const float* b1   = (const float*)d_in[15];
    const float* W2   = (const float*)d_in[16];
    const float* b2   = (const float*)d_in[17];

    float* out = (float*)d_out;

    float* h    = SYM_PTR(g_h);
    float* qh   = SYM_PTR(g_qh);
    float* kh   = SYM_PTR(g_kh);
    float* vh   = SYM_PTR(g_vh);
    float* o    = SYM_PTR(g_o);
    float* t    = SYM_PTR(g_t);
    float* ff   = SYM_PTR(g_ff);
    float* rmax = SYM_PTR(g_rmax);
    float* rinv = SYM_PTR(g_rinv);

    cudaFuncSetAttribute(gemm_tc<128,128,1,true >, cudaFuncAttributeMaxDynamicSharedMemorySize, SMEM_NN128);
    cudaFuncSetAttribute(gemm_tc<128,128,0,false>, cudaFuncAttributeMaxDynamicSharedMemorySize, SMEM_NN128);
    cudaFuncSetAttribute(attn_stats_kernel, cudaFuncAttributeMaxDynamicSharedMemorySize, SMEM_STATS);
    cudaFuncSetAttribute(attn_av_kernel,    cudaFuncAttributeMaxDynamicSharedMemorySize, SMEM_AV);

    embed_kernel<<<BSn, 256>>>(x, emb, h);

    for (int l = 0; l < Ln; l++) {
        const float* Wq_l = Wq + (long)l*Dn*Dn; const float* bq_l = bq + (long)l*Dn;
        const float* Wk_l = Wk + (long)l*Dn*Dn; const float* bk_l = bk + (long)l*Dn;
        const float* Wv_l = Wv + (long)l*Dn*Dn; const float* bv_l = bv + (long)l*Dn;
        const float* Wo_l = Wo + (long)l*Dn*Dn; const float* bo_l = bo + (long)l*Dn;
        const float* W1_l = W1 + (long)l*Dn*Fn; const float* b1_l = b1 + (long)l*Fn;
        const float* W2_l = W2 + (long)l*Fn*Dn; const float* b2_l = b2 + (long)l*Dn;
        float* maps = out + (long)BSn*Dn + (long)l*Bn*Hn*Sn*Sn;

        // QKV fused -> head layout
        {
            dim3 grid(Dn/128, BSn/128, 3);
            gemm_tc<128,128,1,true><<<grid,256,SMEM_NN128>>>(
                h, Wq_l, Wk_l, Wv_l, bq_l, bk_l, bv_l, qh, kh, vh,
                BSn, Dn, Dn, Dn, Dn, 0, 0);
        }
        // attention: stats pass then probs+AV pass (no raw score materialization)
        {
            dim3 grid(NKT, BHn);
            attn_stats_kernel<<<grid,256,SMEM_STATS>>>(qh, kh, rmax, rinv);
            attn_av_kernel<<<grid,256,SMEM_AV>>>(qh, kh, vh, rmax, rinv, maps, o);
        }
        // attn_out = o @ Wo + bo
        {
            dim3 grid(Dn/128, BSn/128, 1);
            gemm_tc<128,128,0,false><<<grid,256,SMEM_NN128>>>(
                o, Wo_l, nullptr, nullptr, bo_l, nullptr, nullptr,
                t, nullptr, nullptr,
                BSn, Dn, Dn, Dn, Dn, Dn, 0);
        }
        add_ln_kernel<<<BSn,256>>>(h, t, ln1g + (long)l*Dn, ln1b + (long)l*Dn, h);
        // ff = relu(h @ W1 + b1)
        {
            dim3 grid(Fn/128, BSn/128, 1);
            gemm_tc<128,128,0,false><<<grid,256,SMEM_NN128>>>(
                h, W1_l, nullptr, nullptr, b1_l, nullptr, nullptr,
                ff, nullptr, nullptr,
                BSn, Fn, Dn, Dn, Fn, Fn, 1);
        }
        // t = ff @ W2 + b2
        {
            dim3 grid(Dn/128, BSn/128, 1);
            gemm_tc<128,128,0,false><<<grid,256,SMEM_NN128>>>(
                ff, W2_l, nullptr, nullptr, b2_l, nullptr, nullptr,
                t, nullptr, nullptr,
                BSn, Dn, Fn, Fn, Dn, Dn, 0);
        }
        float* ln_dst = (l == Ln-1) ? out : h;
        add_ln_kernel<<<BSn,256>>>(h, t, ln2g + (long)l*Dn, ln2b + (long)l*Dn, ln_dst);
    }
}

// round 7
// speedup vs baseline: 1.2523x; 1.2523x over previous
#include <cuda_runtime.h>
#include <mma.h>
#include <math.h>
#include <cstdint>
#include <stdint.h>

using namespace nvcuda;

#define Bn 2
#define Sn 2048
#define Dn 768
#define Hn 12
#define DHn 64
#define Fn 3072
#define Ln 2
#define BSn (Bn*Sn)
#define BHn (Bn*Hn)
#define NTILES 16              // Sn / 128 score column tiles

// ---------------- scratch ----------------
__device__ float g_h  [BSn*Dn];
__device__ float g_qh [BSn*Dn];
__device__ float g_kh [BSn*Dn];
__device__ float g_vh [BSn*Dn];
__device__ float g_o  [BSn*Dn];
__device__ float g_t  [BSn*Dn];
__device__ float g_ff [BSn*Fn];
__device__ float g_smax[BHn*Sn*NTILES];
__device__ float g_ssum[BHn*Sn*NTILES];
__device__ float g_rmax[BHn*Sn];
__device__ float g_rinv[BHn*Sn];

// ---------------- cp.async helpers ----------------
__device__ __forceinline__ void cp_async16(uint32_t saddr, const void* gaddr) {
    asm volatile("cp.async.cg.shared.global [%0], [%1], 16;\n" :: "r"(saddr), "l"(gaddr));
}
#define CP_COMMIT() asm volatile("cp.async.commit_group;\n" ::)
#define CP_WAIT1()  asm volatile("cp.async.wait_group 1;\n" ::)
#define CP_WAIT0()  asm volatile("cp.async.wait_group 0;\n" ::)

// ---------------- embedding + sinusoidal PE ----------------
__global__ void embed_kernel(const int* __restrict__ x, const float* __restrict__ emb,
                             float* __restrict__ h)
{
    int row = blockIdx.x;
    int s   = row % Sn;
    long tok = x[row];
    const float* er = emb + tok * (long)Dn;
    float* hr = h + (long)row * Dn;
    const float c = -logf(10000.0f) / (float)Dn;
    for (int j = threadIdx.x; j < Dn; j += blockDim.x) {
        float div = expf((float)(j & ~1) * c);
        float ang = (float)s * div;
        float pe = (j & 1) ? cosf(ang) : sinf(ang);
        hr[j] = er[j] + pe;
    }
}

// ---------------- pipelined TF32 tensor-core GEMM ----------------
// NOTE: no __float_to_tf32 in the mainloop — HMMA.TF32 truncates fp32 bits
// (bits [31:13]); error <= 2x RN rounding, well inside the 1e-3 budget.
// MODE: 0 plain, 1 heads (QKV -> [b,h,s,d]), 2 merge (AV -> [b,s,D])
// MULTI: z selects among {B0,B1,B2}; STATS: scores epilogue emits softmax partials;
// SMAX: A is raw scores -> normalize on the fly + write probs back to A.
template<int BM, int BN, bool NT, int MODE, bool MULTI, bool STATS, bool SMAX>
__global__ __launch_bounds__(256, 2)
void gemm_tc(const float* __restrict__ A,
             const float* B0, const float* B1, const float* B2,
             const float* bias0, const float* bias1, const float* bias2,
             float* C0, float* C1, float* C2,
             int M, int N, int K, int lda, int ldb, int ldc,
             long sA, long sB, long sC, float alpha, int relu,
             float* st_max, float* st_sum,
             const float* r_max, const float* r_inv)
{
    constexpr int BK = 32;
    constexpr int STAGES = 3;
    constexpr int LDA_S = BK + 4;
    constexpr int LDB_S = NT ? (BK + 4) : (BN + 4);
    constexpr int BROWS = NT ? BN : BK;
    constexpr int LDC_S = BN + 4;
    constexpr int WARPS_M = 4, WARPS_N = 2;
    constexpr int WM = BM / WARPS_M;
    constexpr int WN = BN / WARPS_N;
    constexpr int FM = WM / 16;
    constexpr int FN = WN / 16;

    extern __shared__ char smem_raw[];
    float* As = (float*)smem_raw;                       // [STAGES][BM][LDA_S]
    float* Bs = As + STAGES * BM * LDA_S;               // [STAGES][BROWS][LDB_S]
    float* sm_rmax = Bs + STAGES * BROWS * LDB_S;       // [BM]   (SMAX only)
    float* sm_rinv = sm_rmax + BM;                      // [BM]
    float* Cs = (float*)smem_raw;                       // epilogue alias

    const int z = blockIdx.z;
    const float* Bm; const float* bias; float* C;
    if (MULTI) {
        Bm   = (z == 0) ? B0 : ((z == 1) ? B1 : B2);
        bias = (z == 0) ? bias0 : ((z == 1) ? bias1 : bias2);
        C    = (z == 0) ? C0 : ((z == 1) ? C1 : C2);
    } else {
        Bm   = B0 + z * sB;
        bias = bias0;
        C    = C0 + z * sC;
        A   += z * sA;
    }

    const int bm = blockIdx.y * BM;
    const int bn = blockIdx.x * BN;
    const int tid = threadIdx.x;
    const int warp = tid >> 5;
    const int lane = tid & 31;
    const int wm = (warp % WARPS_M) * WM;
    const int wn = (warp / WARPS_M) * WN;

    if (SMAX) {           // preload row softmax stats (visible after first barrier)
        if (tid < BM) {
            sm_rmax[tid] = r_max[(long)z * Sn + bm + tid];
            sm_rinv[tid] = r_inv[(long)z * Sn + bm + tid];
        }
    }

    const uint32_t sAs = (uint32_t)__cvta_generic_to_shared(As);
    const uint32_t sBs = (uint32_t)__cvta_generic_to_shared(Bs);

    wmma::fragment<wmma::accumulator, 16, 16, 8, float> acc[FM][FN];
#pragma unroll
    for (int i = 0; i < FM; i++)
#pragma unroll
        for (int j = 0; j < FN; j++) wmma::fill_fragment(acc[i][j], 0.0f);

    const int kIters = K / BK;

    auto load_stage = [&](int st, int ki) {
        if (ki >= kIters) return;
        const int k0 = ki * BK;
        constexpr int NVA = BM * BK / 4;
#pragma unroll
        for (int e = tid; e < NVA; e += 256) {
            int m  = e / (BK / 4);
            int kv = (e % (BK / 4)) * 4;
            cp_async16(sAs + ((st * BM + m) * LDA_S + kv) * 4,
                       A + (long)(bm + m) * lda + k0 + kv);
        }
        if (!NT) {
            constexpr int NVB = BK * BN / 4;
#pragma unroll
            for (int e = tid; e < NVB; e += 256) {
                int k  = e / (BN / 4);
                int nv = (e % (BN / 4)) * 4;
                cp_async16(sBs + ((st * BROWS + k) * LDB_S + nv) * 4,
                           Bm + (long)(k0 + k) * ldb + bn + nv);
            }
        } else {
            constexpr int NVB = BN * BK / 4;
#pragma unroll
            for (int e = tid; e < NVB; e += 256) {
                int n  = e / (BK / 4);
                int kv = (e % (BK / 4)) * 4;
                cp_async16(sBs + ((st * BROWS + n) * LDB_S + kv) * 4,
                           Bm + (long)(bn + n) * ldb + k0 + kv);
            }
        }
    };

    for (int s = 0; s < STAGES - 1; s++) { load_stage(s, s); CP_COMMIT(); }

    for (int ki = 0; ki < kIters; ki++) {
        CP_WAIT1();
        __syncthreads();
        load_stage((ki + STAGES - 1) % STAGES, ki + STAGES - 1);
        CP_COMMIT();

        const int st = ki % STAGES;
        float* Ast = As + st * BM * LDA_S;
        const float* Bst = Bs + st * BROWS * LDB_S;

        if (SMAX) {
            // normalize raw scores in smem + write probabilities back to gmem
            const int k0 = ki * BK;
            float* Awb = const_cast<float*>(A);
            constexpr int NVA = BM * BK / 4;
#pragma unroll
            for (int e = tid; e < NVA; e += 256) {
                int m  = e >> 3;
                int kv = (e & 7) * 4;
                float4 s4 = *(float4*)&Ast[m * LDA_S + kv];
                float mx = sm_rmax[m], inv = sm_rinv[m];
                s4.x = __expf(s4.x - mx) * inv;
                s4.y = __expf(s4.y - mx) * inv;
                s4.z = __expf(s4.z - mx) * inv;
                s4.w = __expf(s4.w - mx) * inv;
                *(float4*)&Ast[m * LDA_S + kv] = s4;
                *(float4*)&Awb[(long)(bm + m) * lda + k0 + kv] = s4;
            }
            __syncthreads();
        }

#pragma unroll
        for (int kf = 0; kf < BK / 8; kf++) {
            wmma::fragment<wmma::matrix_a, 16, 16, 8, wmma::precision::tf32, wmma::row_major> af[FM];
#pragma unroll
            for (int i = 0; i < FM; i++)
                wmma::load_matrix_sync(af[i], Ast + (wm + i * 16) * LDA_S + kf * 8, LDA_S);
            if (!NT) {
                wmma::fragment<wmma::matrix_b, 16, 16, 8, wmma::precision::tf32, wmma::row_major> bf[FN];
#pragma unroll
                for (int j = 0; j < FN; j++)
                    wmma::load_matrix_sync(bf[j], Bst + (kf * 8) * LDB_S + wn + j * 16, LDB_S);
#pragma unroll
                for (int i = 0; i < FM; i++)
#pragma unroll
                    for (int j = 0; j < FN; j++)
                        wmma::mma_sync(acc[i][j], af[i], bf[j], acc[i][j]);
            } else {
                wmma::fragment<wmma::matrix_b, 16, 16, 8, wmma::precision::tf32, wmma::col_major> bf[FN];
#pragma unroll
                for (int j = 0; j < FN; j++)
                    wmma::load_matrix_sync(bf[j], Bst + (wn + j * 16) * LDB_S + kf * 8, LDB_S);
#pragma unroll
                for (int i = 0; i < FM; i++)
#pragma unroll
                    for (int j = 0; j < FN; j++)
                        wmma::mma_sync(acc[i][j], af[i], bf[j], acc[i][j]);
            }
        }
    }

    CP_WAIT0();
    __syncthreads();

#pragma unroll
    for (int i = 0; i < FM; i++)
#pragma unroll
        for (int j = 0; j < FN; j++)
            wmma::store_matrix_sync(Cs + (wm + i * 16) * LDC_S + wn + j * 16,
                                    acc[i][j], LDC_S, wmma::mem_row_major);
    __syncthreads();

    constexpr int NVC = BM * BN / 4;
    if (STATS) {
        // scores epilogue: store raw tile + per-(row, tile) max & sumexp
#pragma unroll
        for (int p = 0; p < NVC / 256; p++) {
            int e  = tid + p * 256;
            int m  = e / (BN / 4);
            int nv = (e % (BN / 4)) * 4;
            float4 v = *(const float4*)&Cs[m * LDC_S + nv];
            v.x *= alpha; v.y *= alpha; v.z *= alpha; v.w *= alpha;
            *(float4*)&C[(long)(bm + m) * ldc + bn + nv] = v;
            float lmax = fmaxf(fmaxf(v.x, v.y), fmaxf(v.z, v.w));
#pragma unroll
            for (int o = 16; o > 0; o >>= 1)
                lmax = fmaxf(lmax, __shfl_xor_sync(0xffffffffu, lmax, o));
            float lsum = __expf(v.x - lmax) + __expf(v.y - lmax) +
                         __expf(v.z - lmax) + __expf(v.w - lmax);
#pragma unroll
            for (int o = 16; o > 0; o >>= 1)
                lsum += __shfl_xor_sync(0xffffffffu, lsum, o);
            if (lane == 0) {
                long idx = ((long)z * Sn + bm + m) * NTILES + blockIdx.x;
                st_max[idx] = lmax;
                st_sum[idx] = lsum;
            }
        }
    } else {
#pragma unroll 4
        for (int e = tid; e < NVC; e += 256) {
            int m  = e / (BN / 4);
            int nv = (e % (BN / 4)) * 4;
            float4 v = *(const float4*)&Cs[m * LDC_S + nv];
            if (alpha != 1.0f) { v.x *= alpha; v.y *= alpha; v.z *= alpha; v.w *= alpha; }
            if (bias) {
                int c = bn + nv;
                v.x += bias[c]; v.y += bias[c + 1]; v.z += bias[c + 2]; v.w += bias[c + 3];
            }
            if (relu) {
                v.x = fmaxf(v.x, 0.f); v.y = fmaxf(v.y, 0.f);
                v.z = fmaxf(v.z, 0.f); v.w = fmaxf(v.w, 0.f);
            }
            if (MODE == 0) {
                *(float4*)&C[(long)(bm + m) * ldc + bn + nv] = v;
            } else if (MODE == 1) {
                int r = bm + m, c = bn + nv;
                int b = r >> 11, s = r & (Sn - 1);
                int hh = c >> 6, d = c & 63;
                *(float4*)&C[((((long)b * Hn + hh) * Sn + s) << 6) + d] = v;
            } else {
                int b = z / Hn, hh = z % Hn;
                *(float4*)&C[((long)(b * Sn + bm + m)) * Dn + hh * DHn + bn + nv] = v;
            }
        }
    }
}

// ---------------- combine per-tile stats into row max / inv-sum ----------------
__global__ void stats_reduce(const float* __restrict__ smax, const float* __restrict__ ssum,
                             float* __restrict__ rmax, float* __restrict__ rinv)
{
    long row = (long)blockIdx.x * blockDim.x + threadIdx.x;
    if (row >= (long)BHn * Sn) return;
    float M = -1e30f;
#pragma unroll
    for (int t = 0; t < NTILES; t++) M = fmaxf(M, smax[row * NTILES + t]);
    float S = 0.f;
#pragma unroll
    for (int t = 0; t < NTILES; t++) S += ssum[row * NTILES + t] * __expf(smax[row * NTILES + t] - M);
    rmax[row] = M;
    rinv[row] = 1.f / S;
}

// ---------------- residual add + LayerNorm ----------------
__global__ void add_ln_kernel(const float* __restrict__ x, const float* __restrict__ d,
                              const float* __restrict__ g, const float* __restrict__ bb,
                              float* __restrict__ out)
{
    int row = blockIdx.x;
    int t = threadIdx.x;
    __shared__ float red[256];
    float v[3];
    float s = 0.f;
#pragma unroll
    for (int i = 0; i < 3; i++) {
        int c = t + i*256;
        v[i] = x[(long)row*Dn + c] + d[(long)row*Dn + c];
        s += v[i];
    }
    red[t] = s; __syncthreads();
    for (int o = 128; o > 0; o >>= 1) { if (t < o) red[t] += red[t+o]; __syncthreads(); }
    float mu = red[0] / (float)Dn;
    __syncthreads();
    float s2 = 0.f;
#pragma unroll
    for (int i = 0; i < 3; i++) { float dv = v[i] - mu; s2 += dv*dv; }
    red[t] = s2; __syncthreads();
    for (int o = 128; o > 0; o >>= 1) { if (t < o) red[t] += red[t+o]; __syncthreads(); }
    float inv = rsqrtf(red[0] / (float)Dn + 1e-5f);
    __syncthreads();
#pragma unroll
    for (int i = 0; i < 3; i++) {
        int c = t + i*256;
        out[(long)row*Dn + c] = (v[i] - mu) * inv * g[c] + bb[c];
    }
}

// ---------------- host side ----------------
#define SYM_PTR(sym) ([]{ void* p_; cudaGetSymbolAddress(&p_, sym); return (float*)p_; }())

#define SMEM_NN128 ((3*(128*36 + 32*132))*4)            // 105984
#define SMEM_NT128 ((3*(128*36 + 128*36))*4)            // 110592
#define SMEM_NN64  ((3*(128*36 + 32*68))*4 + 128*2*4)   // 82432 (incl. row stats)

extern "C" void kernel_launch(void* const* d_in, const int* in_sizes, int n_in,
                              void* d_out, int out_size)
{
    const int*   x    = (const int*)  d_in[0];
    const float* emb  = (const float*)d_in[1];
    const float* Wq   = (const float*)d_in[2];
    const float* bq   = (const float*)d_in[3];
    const float* Wk   = (const float*)d_in[4];
    const float* bk   = (const float*)d_in[5];
    const float* Wv   = (const float*)d_in[6];
    const float* bv   = (const float*)d_in[7];
    const float* Wo   = (const float*)d_in[8];
    const float* bo   = (const float*)d_in[9];
    const float* ln1g = (const float*)d_in[10];
    const float* ln1b = (const float*)d_in[11];
    const float* ln2g = (const float*)d_in[12];
    const float* ln2b = (const float*)d_in[13];
    const float* W1   = (const float*)d_in[14];
    const float* b1   = (const float*)d_in[15];
    const float* W2   = (const float*)d_in[16];
    const float* b2   = (const float*)d_in[17];

    float* out = (float*)d_out;

    float* h   = SYM_PTR(g_h);
    float* qh  = SYM_PTR(g_qh);
    float* kh  = SYM_PTR(g_kh);
    float* vh  = SYM_PTR(g_vh);
    float* o   = SYM_PTR(g_o);
    float* t   = SYM_PTR(g_t);
    float* ff  = SYM_PTR(g_ff);
    float* smax = SYM_PTR(g_smax);
    float* ssum = SYM_PTR(g_ssum);
    float* rmax = SYM_PTR(g_rmax);
    float* rinv = SYM_PTR(g_rinv);

    cudaFuncSetAttribute(gemm_tc<128,128,false,1,true ,false,false>, cudaFuncAttributeMaxDynamicSharedMemorySize, SMEM_NN128);
    cudaFuncSetAttribute(gemm_tc<128,128,false,0,false,false,false>, cudaFuncAttributeMaxDynamicSharedMemorySize, SMEM_NN128);
    cudaFuncSetAttribute(gemm_tc<128,128,true ,0,false,true ,false>, cudaFuncAttributeMaxDynamicSharedMemorySize, SMEM_NT128);
    cudaFuncSetAttribute(gemm_tc<128,64 ,false,2,false,false,true >, cudaFuncAttributeMaxDynamicSharedMemorySize, SMEM_NN64);

    embed_kernel<<<BSn, 256>>>(x, emb, h);

    for (int l = 0; l < Ln; l++) {
        const float* Wq_l = Wq + (long)l*Dn*Dn; const float* bq_l = bq + (long)l*Dn;
        const float* Wk_l = Wk + (long)l*Dn*Dn; const float* bk_l = bk + (long)l*Dn;
        const float* Wv_l = Wv + (long)l*Dn*Dn; const float* bv_l = bv + (long)l*Dn;
        const float* Wo_l = Wo + (long)l*Dn*Dn; const float* bo_l = bo + (long)l*Dn;
        const float* W1_l = W1 + (long)l*Dn*Fn; const float* b1_l = b1 + (long)l*Fn;
        const float* W2_l = W2 + (long)l*Fn*Dn; const float* b2_l = b2 + (long)l*Dn;
        float* maps = out + (long)BSn*Dn + (long)l*Bn*Hn*Sn*Sn;

        // QKV fused -> head layout
        {
            dim3 grid(Dn/128, BSn/128, 3);
            gemm_tc<128,128,false,1,true,false,false><<<grid,256,SMEM_NN128>>>(
                h, Wq_l, Wk_l, Wv_l, bq_l, bk_l, bv_l, qh, kh, vh,
                BSn, Dn, Dn, Dn, Dn, 0, 0,0,0, 1.f, 0,
                nullptr, nullptr, nullptr, nullptr);
        }
        // scores = Q K^T / 8 -> maps (raw) + softmax partial stats
        {
            dim3 grid(Sn/128, Sn/128, BHn);
            gemm_tc<128,128,true,0,false,true,false><<<grid,256,SMEM_NT128>>>(
                qh, kh, nullptr, nullptr, nullptr, nullptr, nullptr,
                maps, nullptr, nullptr,
                Sn, Sn, DHn, DHn, DHn, Sn,
                (long)Sn*DHn, (long)Sn*DHn, (long)Sn*Sn, 0.125f, 0,
                smax, ssum, nullptr, nullptr);
        }
        stats_reduce<<<(BHn*Sn + 255)/256, 256>>>(smax, ssum, rmax, rinv);
        // O = softmax(scores) @ V  (normalize on the fly, write probs back to maps)
        {
            dim3 grid(1, Sn/128, BHn);
            gemm_tc<128,64,false,2,false,false,true><<<grid,256,SMEM_NN64>>>(
                maps, vh, nullptr, nullptr, nullptr, nullptr, nullptr,
                o, nullptr, nullptr,
                Sn, DHn, Sn, Sn, DHn, 0,
                (long)Sn*Sn, (long)Sn*DHn, 0, 1.f, 0,
                nullptr, nullptr, rmax, rinv);
        }
        // attn_out = o @ Wo + bo
        {
            dim3 grid(Dn/128, BSn/128, 1);
            gemm_tc<128,128,false,0,false,false,false><<<grid,256,SMEM_NN128>>>(
                o, Wo_l, nullptr, nullptr, bo_l, nullptr, nullptr,
                t, nullptr, nullptr,
                BSn, Dn, Dn, Dn, Dn, Dn, 0,0,0, 1.f, 0,
                nullptr, nullptr, nullptr, nullptr);
        }
        add_ln_kernel<<<BSn,256>>>(h, t, ln1g + (long)l*Dn, ln1b + (long)l*Dn, h);
        // ff = relu(h @ W1 + b1)
        {
            dim3 grid(Fn/128, BSn/128, 1);
            gemm_tc<128,128,false,0,false,false,false><<<grid,256,SMEM_NN128>>>(
                h, W1_l, nullptr, nullptr, b1_l, nullptr, nullptr,
                ff, nullptr, nullptr,
                BSn, Fn, Dn, Dn, Fn, Fn, 0,0,0, 1.f, 1,
                nullptr, nullptr, nullptr, nullptr);
        }
        // t = ff @ W2 + b2
        {
            dim3 grid(Dn/128, BSn/128, 1);
            gemm_tc<128,128,false,0,false,false,false><<<grid,256,SMEM_NN128>>>(
                ff, W2_l, nullptr, nullptr, b2_l, nullptr, nullptr,
                t, nullptr, nullptr,
                BSn, Dn, Fn, Fn, Dn, Dn, 0,0,0, 1.f, 0,
                nullptr, nullptr, nullptr, nullptr);
        }
        float* ln_dst = (l == Ln-1) ? out : h;
        add_ln_kernel<<<BSn,256>>>(h, t, ln2g + (long)l*Dn, ln2b + (long)l*Dn, ln_dst);
    }
}